// round 3
// baseline (speedup 1.0000x reference)
#include <cuda_runtime.h>

#define Bq 8
#define Tq 2048
#define Dq 128
#define Kq 32
#define Nq 32
#define HNq 16
#define Mq 128
#define Lq 32
#define Cq 64   // Tq / Lq

// ---------------- device scratch (static: no allocation in kernel_launch) ----
__device__ float  g_xp[Bq][Kq][Tq];        // projected input, [b][k][t] (t contiguous)
__device__ float2 g_lam[Kq][Nq];           // lambda
__device__ float2 g_lamL[Kq][Nq];          // lambda^Lq
__device__ float2 g_Bp[Kq][Nq];            // B' coefficients (complex)
__device__ float2 g_P[Bq][Kq][Cq][Nq];     // chunk partial sums
__device__ float2 g_S[Bq][Kq][Cq][Nq];     // state at chunk starts
__device__ float  g_Cr[Kq][Nq][Mq];        // Re(Cp)
__device__ float  g_Cin[Kq][Nq][Mq];       // -Im(Cp)  (negated so readout is 2 packed FMAs)

// ---------------- K1: lambda, lambda^L, Bp (double precision, tiny) ----------
__global__ void k_pre(const float* __restrict__ theta) {
    __shared__ float ph[Kq][Nq];
    int k = threadIdx.y;   // 0..31
    int j = threadIdx.x;   // 0..31
    float th = (j < HNq) ? theta[k * HNq + j] : -theta[k * HNq + (j - HNq)];
    ph[k][j] = th;
    __syncthreads();

    double phj = (double)ph[k][j];
    g_lam[k][j]  = make_float2((float)cos(phj), (float)sin(phj));
    double aL = phj * (double)Lq;
    g_lamL[k][j] = make_float2((float)cos(aL), (float)sin(aL));

    // lnBp[j] = -sum_{i != j} log(1 - lam_i / lam_j), complex log
    double lr = 0.0, li = 0.0;
    for (int i = 0; i < Nq; i++) {
        if (i == j) continue;
        double d  = (double)ph[k][i] - phj;       // ratio = e^{i d}
        double wr = 1.0 - cos(d);
        double wi = -sin(d);
        lr += 0.5 * log(wr * wr + wi * wi);
        li += atan2(wi, wr);
    }
    double mag = exp(-lr);
    g_Bp[k][j] = make_float2((float)(mag * cos(-li)), (float)(mag * sin(-li)));
}

// ---------------- K2: Cp = exp(lnC_r + i lnC_i), store Re and -Im ------------
__global__ void k_cp(const float* __restrict__ lnr, const float* __restrict__ lni) {
    int idx = blockIdx.x * blockDim.x + threadIdx.x;
    if (idx >= Kq * Nq * Mq) return;
    float r = expf(lnr[idx]);
    float a = lni[idx];
    ((float*)g_Cr)[idx]  =  r * cosf(a);
    ((float*)g_Cin)[idx] = -r * sinf(a);
}

// ---------------- K3: xp = x @ R, written transposed to [b][k][t] ------------
__global__ void k_xp(const float* __restrict__ x, const float* __restrict__ R) {
    __shared__ float xs[32][129];   // padded: conflict-free
    __shared__ float Rs[Dq][Kq];
    const int b  = blockIdx.y;
    const int t0 = blockIdx.x * 32;
    const int tid = threadIdx.x;

    for (int i = tid; i < Dq * Kq; i += 256) ((float*)Rs)[i] = R[i];
    for (int i = tid; i < 32 * Dq; i += 256) {
        int tl = i >> 7, d = i & 127;
        xs[tl][d] = x[((size_t)b * Tq + t0 + tl) * Dq + d];
    }
    __syncthreads();

    const int tl = tid & 31;
    const int k0 = tid >> 5;   // constant within a warp -> Rs broadcast
    float acc[4] = {0.f, 0.f, 0.f, 0.f};
    for (int d = 0; d < Dq; d++) {
        float xv = xs[tl][d];
        #pragma unroll
        for (int j = 0; j < 4; j++) acc[j] = fmaf(xv, Rs[d][k0 + 8 * j], acc[j]);
    }
    #pragma unroll
    for (int j = 0; j < 4; j++) g_xp[b][k0 + 8 * j][t0 + tl] = acc[j];
}

// ---------------- K4: chunk partials P_c (one warp per (b,k,c)) --------------
__global__ void k_part() {
    int w    = blockIdx.x * 8 + (threadIdx.x >> 5);   // 0 .. B*K*C-1 (16384)
    int lane = threadIdx.x & 31;
    int b = w >> 11;          // / (Kq*Cq)
    int k = (w >> 6) & 31;
    int c = w & 63;

    float2 lam = g_lam[k][lane];
    float2 bp  = g_Bp[k][lane];
    float pr = 0.f, pi = 0.f;
    const float* xp = &g_xp[b][k][c * Lq];
    #pragma unroll 8
    for (int j = 0; j < Lq; j++) {
        float xv = xp[j];
        float nr = fmaf(lam.x, pr, fmaf(-lam.y, pi, bp.x * xv));
        float ni = fmaf(lam.y, pr, fmaf(lam.x, pi, bp.y * xv));
        pr = nr; pi = ni;
    }
    g_P[b][k][c][lane] = make_float2(pr, pi);
}

// ---------------- K5: cross-chunk scan: S_{c+1} = lam^L * S_c + P_c ----------
__global__ void k_scan() {
    int b = blockIdx.x >> 5, k = blockIdx.x & 31, n = threadIdx.x;
    float2 lL = g_lamL[k][n];
    float sr = 0.f, si = 0.f;
    for (int c = 0; c < Cq; c++) {
        g_S[b][k][c][n] = make_float2(sr, si);
        float2 p = g_P[b][k][c][n];
        float nr = fmaf(lL.x, sr, fmaf(-lL.y, si, p.x));
        float ni = fmaf(lL.y, sr, fmaf(lL.x, si, p.y));
        sr = nr; si = ni;
    }
}

// ---------------- K6: base output = (1/K) * xp @ D + Do ----------------------
__global__ void k_dterm(const float* __restrict__ Dmat, const float* __restrict__ Dov,
                        float* __restrict__ out) {
    __shared__ float sxp[8][33];
    const int m   = threadIdx.x;
    const int bt0 = blockIdx.x * 8;
    for (int i = threadIdx.x; i < 8 * Kq; i += 128) {
        int r = i >> 5, k = i & 31;
        int bt = bt0 + r;
        sxp[r][k] = g_xp[bt >> 11][k][bt & 2047];
    }
    __syncthreads();
    float dov = Dov[m];
    for (int r = 0; r < 8; r++) {
        float acc = 0.f;
        #pragma unroll 8
        for (int k = 0; k < Kq; k++) acc = fmaf(sxp[r][k], Dmat[k * Mq + m], acc);
        out[(size_t)(bt0 + r) * Mq + m] = fmaf(acc, 1.0f / 32.0f, dov);
    }
}

// ---------------- K7: fused in-chunk replay + packed-fp32 readout ------------
__device__ __forceinline__ void scan_chunk(int k, int buf, int b, int c, int lane,
                                           float4 (*sd)[Lq][Nq]) {
    float2 lam = g_lam[k][lane];
    float2 bp  = g_Bp[k][lane];
    float2 s   = g_S[b][k][c][lane];
    sd[buf][0][lane] = make_float4(s.x, s.x, s.y, s.y);
    const float* xp = &g_xp[b][k][c * Lq];
    #pragma unroll
    for (int i = 1; i < Lq; i++) {
        float xv = xp[i - 1];
        float nr = fmaf(lam.x, s.x, fmaf(-lam.y, s.y, bp.x * xv));
        float ni = fmaf(lam.y, s.x, fmaf(lam.x, s.y, bp.y * xv));
        s.x = nr; s.y = ni;
        sd[buf][i][lane] = make_float4(s.x, s.x, s.y, s.y);
    }
}

__global__ void __launch_bounds__(288, 1) k_main(float* __restrict__ out) {
    __shared__ float4 sdup[2][Lq][Nq];   // state chunk, duplicated (sr,sr,si,si)
    const int c   = blockIdx.x;
    const int b   = blockIdx.y;
    const int tid = threadIdx.x;
    const int g   = (tid >> 6) & 3;  // i-group (0..3), constant within warp
    const int p   = tid & 63;        // m-pair index

    if (tid >= 256) scan_chunk(0, 0, b, c, tid - 256, sdup);
    __syncthreads();

    unsigned long long accA[8], accB[8];
    #pragma unroll
    for (int ii = 0; ii < 8; ii++) { accA[ii] = 0ull; accB[ii] = 0ull; }

    for (int k = 0; k < Kq; k++) {
        const int buf = k & 1;
        if (tid < 256) {
            // load Cp for this k into packed registers (L1 reuse across i-groups)
            unsigned long long crp[Nq], cip[Nq];
            const float2* crsrc = reinterpret_cast<const float2*>(&g_Cr[k][0][0]) + p;
            const float2* cisrc = reinterpret_cast<const float2*>(&g_Cin[k][0][0]) + p;
            #pragma unroll
            for (int n = 0; n < Nq; n++) {
                crp[n] = *reinterpret_cast<const unsigned long long*>(crsrc + (size_t)n * 64);
                cip[n] = *reinterpret_cast<const unsigned long long*>(cisrc + (size_t)n * 64);
            }
            const ulonglong2* sbase =
                reinterpret_cast<const ulonglong2*>(&sdup[buf][g * 8][0]);
            #pragma unroll
            for (int n = 0; n < Nq; n++) {
                #pragma unroll
                for (int ii = 0; ii < 8; ii++) {
                    ulonglong2 v = sbase[ii * Nq + n];   // (sr,sr),(si,si)
                    asm("fma.rn.f32x2 %0, %1, %2, %0;" : "+l"(accA[ii]) : "l"(v.x), "l"(crp[n]));
                    asm("fma.rn.f32x2 %0, %1, %2, %0;" : "+l"(accB[ii]) : "l"(v.y), "l"(cip[n]));
                }
            }
        } else if (k + 1 < Kq) {
            scan_chunk(k + 1, (k + 1) & 1, b, c, tid - 256, sdup);
        }
        __syncthreads();
    }

    if (tid < 256) {
        const float inv = 1.0f / 32.0f;
        #pragma unroll
        for (int ii = 0; ii < 8; ii++) {
            unsigned long long tot;
            asm("add.rn.f32x2 %0, %1, %2;" : "=l"(tot) : "l"(accA[ii]), "l"(accB[ii]));
            float2 r = *reinterpret_cast<float2*>(&tot);
            int t = c * Lq + g * 8 + ii;
            float2* op = reinterpret_cast<float2*>(out + ((size_t)b * Tq + t) * Mq + 2 * p);
            float2 cur = *op;                 // base from k_dterm
            cur.x = fmaf(r.x, inv, cur.x);
            cur.y = fmaf(r.y, inv, cur.y);
            *op = cur;
        }
    }
}

// ---------------- launch ------------------------------------------------------
extern "C" void kernel_launch(void* const* d_in, const int* in_sizes, int n_in,
                              void* d_out, int out_size) {
    const float* x     = (const float*)d_in[0];
    const float* R     = (const float*)d_in[1];
    const float* theta = (const float*)d_in[2];
    const float* lnC_r = (const float*)d_in[3];
    const float* lnC_i = (const float*)d_in[4];
    const float* Dmat  = (const float*)d_in[5];
    const float* Dov   = (const float*)d_in[6];
    float* out = (float*)d_out;

    k_pre<<<1, dim3(32, 32)>>>(theta);
    k_cp<<<(Kq * Nq * Mq + 255) / 256, 256>>>(lnC_r, lnC_i);
    k_xp<<<dim3(Tq / 32, Bq), 256>>>(x, R);
    k_part<<<(Bq * Kq * Cq) / 8, 256>>>();
    k_scan<<<Bq * Kq, 32>>>();
    k_dterm<<<(Bq * Tq) / 8, 128>>>(Dmat, Dov, out);
    k_main<<<dim3(Cq, Bq), 288>>>(out);
}

// round 5
// speedup vs baseline: 1.0200x; 1.0200x over previous
#include <cuda_runtime.h>

#define Bq 8
#define Tq 2048
#define Dq 128
#define Kq 32
#define Nq 32
#define HNq 16
#define Mq 128
#define Lq 32
#define Cq 64   // Tq / Lq

// ---------------- device scratch (static: no allocation in kernel_launch) ----
__device__ float  g_xp[Bq][Kq][Tq];        // projected input, [b][k][t] (t contiguous)
__device__ float2 g_lam[Kq][Nq];           // lambda
__device__ float2 g_lamL[Kq][Nq];          // lambda^Lq
__device__ float2 g_Bp[Kq][Nq];            // B' coefficients (complex)
__device__ float2 g_P[Bq][Kq][Cq][Nq];     // chunk partial sums
__device__ float2 g_S[Bq][Kq][Cq][Nq];     // state at chunk starts
__device__ float  g_Cr[Kq][Nq][Mq];        // Re(Cp)
__device__ float  g_Cin[Kq][Nq][Mq];       // -Im(Cp)  (negated so readout is 2 packed FMAs)

// ---------------- K1: lambda, lambda^L, Bp (double precision, tiny) ----------
__global__ void k_pre(const float* __restrict__ theta) {
    __shared__ float ph[Kq][Nq];
    int k = threadIdx.y;   // 0..31
    int j = threadIdx.x;   // 0..31
    float th = (j < HNq) ? theta[k * HNq + j] : -theta[k * HNq + (j - HNq)];
    ph[k][j] = th;
    __syncthreads();

    double phj = (double)ph[k][j];
    g_lam[k][j]  = make_float2((float)cos(phj), (float)sin(phj));
    double aL = phj * (double)Lq;
    g_lamL[k][j] = make_float2((float)cos(aL), (float)sin(aL));

    // lnBp[j] = -sum_{i != j} log(1 - lam_i / lam_j), complex log
    double lr = 0.0, li = 0.0;
    for (int i = 0; i < Nq; i++) {
        if (i == j) continue;
        double d  = (double)ph[k][i] - phj;       // ratio = e^{i d}
        double wr = 1.0 - cos(d);
        double wi = -sin(d);
        lr += 0.5 * log(wr * wr + wi * wi);
        li += atan2(wi, wr);
    }
    double mag = exp(-lr);
    g_Bp[k][j] = make_float2((float)(mag * cos(-li)), (float)(mag * sin(-li)));
}

// ---------------- K2: Cp = exp(lnC_r + i lnC_i), store Re and -Im ------------
__global__ void k_cp(const float* __restrict__ lnr, const float* __restrict__ lni) {
    int idx = blockIdx.x * blockDim.x + threadIdx.x;
    if (idx >= Kq * Nq * Mq) return;
    float r = expf(lnr[idx]);
    float a = lni[idx];
    ((float*)g_Cr)[idx]  =  r * cosf(a);
    ((float*)g_Cin)[idx] = -r * sinf(a);
}

// ---------------- K3: xp = x @ R, written transposed to [b][k][t] ------------
__global__ void k_xp(const float* __restrict__ x, const float* __restrict__ R) {
    __shared__ float xs[32][129];   // padded: conflict-free
    __shared__ float Rs[Dq][Kq];
    const int b  = blockIdx.y;
    const int t0 = blockIdx.x * 32;
    const int tid = threadIdx.x;

    for (int i = tid; i < Dq * Kq; i += 256) ((float*)Rs)[i] = R[i];
    for (int i = tid; i < 32 * Dq; i += 256) {
        int tl = i >> 7, d = i & 127;
        xs[tl][d] = x[((size_t)b * Tq + t0 + tl) * Dq + d];
    }
    __syncthreads();

    const int tl = tid & 31;
    const int k0 = tid >> 5;   // constant within a warp -> Rs broadcast
    float acc[4] = {0.f, 0.f, 0.f, 0.f};
    for (int d = 0; d < Dq; d++) {
        float xv = xs[tl][d];
        #pragma unroll
        for (int j = 0; j < 4; j++) acc[j] = fmaf(xv, Rs[d][k0 + 8 * j], acc[j]);
    }
    #pragma unroll
    for (int j = 0; j < 4; j++) g_xp[b][k0 + 8 * j][t0 + tl] = acc[j];
}

// ---------------- K4: chunk partials P_c (one warp per (b,k,c)) --------------
__global__ void k_part() {
    int w    = blockIdx.x * 8 + (threadIdx.x >> 5);   // 0 .. B*K*C-1 (16384)
    int lane = threadIdx.x & 31;
    int b = w >> 11;          // / (Kq*Cq)
    int k = (w >> 6) & 31;
    int c = w & 63;

    float2 lam = g_lam[k][lane];
    float2 bp  = g_Bp[k][lane];
    float pr = 0.f, pi = 0.f;
    const float* xp = &g_xp[b][k][c * Lq];
    #pragma unroll 8
    for (int j = 0; j < Lq; j++) {
        float xv = xp[j];
        float nr = fmaf(lam.x, pr, fmaf(-lam.y, pi, bp.x * xv));
        float ni = fmaf(lam.y, pr, fmaf(lam.x, pi, bp.y * xv));
        pr = nr; pi = ni;
    }
    g_P[b][k][c][lane] = make_float2(pr, pi);
}

// ---------------- K5: cross-chunk scan: S_{c+1} = lam^L * S_c + P_c ----------
__global__ void k_scan() {
    int b = blockIdx.x >> 5, k = blockIdx.x & 31, n = threadIdx.x;
    float2 lL = g_lamL[k][n];
    float sr = 0.f, si = 0.f;
    for (int c = 0; c < Cq; c++) {
        g_S[b][k][c][n] = make_float2(sr, si);
        float2 p = g_P[b][k][c][n];
        float nr = fmaf(lL.x, sr, fmaf(-lL.y, si, p.x));
        float ni = fmaf(lL.y, sr, fmaf(lL.x, si, p.y));
        sr = nr; si = ni;
    }
}

// ---------------- K6: base output = (1/K) * xp @ D + Do ----------------------
__global__ void k_dterm(const float* __restrict__ Dmat, const float* __restrict__ Dov,
                        float* __restrict__ out) {
    __shared__ float sxp[8][33];
    const int m   = threadIdx.x;
    const int bt0 = blockIdx.x * 8;
    for (int i = threadIdx.x; i < 8 * Kq; i += 128) {
        int r = i >> 5, k = i & 31;
        int bt = bt0 + r;
        sxp[r][k] = g_xp[bt >> 11][k][bt & 2047];
    }
    __syncthreads();
    float dov = Dov[m];
    for (int r = 0; r < 8; r++) {
        float acc = 0.f;
        #pragma unroll 8
        for (int k = 0; k < Kq; k++) acc = fmaf(sxp[r][k], Dmat[k * Mq + m], acc);
        out[(size_t)(bt0 + r) * Mq + m] = fmaf(acc, 1.0f / 32.0f, dov);
    }
}

// ---------------- K7: fused in-chunk replay + packed-fp32 readout ------------
__device__ __forceinline__ void scan_chunk(int k, int buf, int b, int c, int lane,
                                           float4 (*sd)[Lq][Nq]) {
    float2 lam = g_lam[k][lane];
    float2 bp  = g_Bp[k][lane];
    float2 s   = g_S[b][k][c][lane];
    sd[buf][0][lane] = make_float4(s.x, s.x, s.y, s.y);
    const float* xp = &g_xp[b][k][c * Lq];
    #pragma unroll
    for (int i = 1; i < Lq; i++) {
        float xv = xp[i - 1];
        float nr = fmaf(lam.x, s.x, fmaf(-lam.y, s.y, bp.x * xv));
        float ni = fmaf(lam.y, s.x, fmaf(lam.x, s.y, bp.y * xv));
        s.x = nr; s.y = ni;
        sd[buf][i][lane] = make_float4(s.x, s.x, s.y, s.y);
    }
}

__global__ void __launch_bounds__(288) k_main(float* __restrict__ out) {
    __shared__ float4 sdup[2][Lq][Nq];   // state chunk, duplicated (sr,sr,si,si)
    const int c   = blockIdx.x;
    const int b   = blockIdx.y;
    const int tid = threadIdx.x;
    const int g   = (tid >> 6) & 3;  // i-group (0..3), constant within warp
    const int p   = tid & 63;        // m-pair index

    if (tid >= 256) scan_chunk(0, 0, b, c, tid - 256, sdup);
    __syncthreads();

    unsigned long long accA[8], accB[8];
    #pragma unroll
    for (int ii = 0; ii < 8; ii++) { accA[ii] = 0ull; accB[ii] = 0ull; }

    for (int k = 0; k < Kq; k++) {
        const int buf = k & 1;
        if (tid < 256) {
            const unsigned long long* crsrc =
                reinterpret_cast<const unsigned long long*>(&g_Cr[k][0][0]) + p;
            const unsigned long long* cisrc =
                reinterpret_cast<const unsigned long long*>(&g_Cin[k][0][0]) + p;
            const ulonglong2* sbase =
                reinterpret_cast<const ulonglong2*>(&sdup[buf][g * 8][0]);
            // Only one n's C pair live at a time (2 x 64-bit regs) — no spills.
            // unroll 8 batches 16 LDGs for MLP; L1 reuse across the 4 i-groups.
            #pragma unroll 8
            for (int n = 0; n < Nq; n++) {
                unsigned long long cr = __ldg(crsrc + (size_t)n * 64);
                unsigned long long ci = __ldg(cisrc + (size_t)n * 64);
                #pragma unroll
                for (int ii = 0; ii < 8; ii++) {
                    ulonglong2 v = sbase[ii * Nq + n];   // (sr,sr),(si,si) broadcast LDS.128
                    asm("fma.rn.f32x2 %0, %1, %2, %0;" : "+l"(accA[ii]) : "l"(v.x), "l"(cr));
                    asm("fma.rn.f32x2 %0, %1, %2, %0;" : "+l"(accB[ii]) : "l"(v.y), "l"(ci));
                }
            }
        } else if (k + 1 < Kq) {
            scan_chunk(k + 1, (k + 1) & 1, b, c, tid - 256, sdup);
        }
        __syncthreads();
    }

    if (tid < 256) {
        const float inv = 1.0f / 32.0f;
        #pragma unroll
        for (int ii = 0; ii < 8; ii++) {
            unsigned long long tot;
            asm("add.rn.f32x2 %0, %1, %2;" : "=l"(tot) : "l"(accA[ii]), "l"(accB[ii]));
            float2 r = *reinterpret_cast<float2*>(&tot);
            int t = c * Lq + g * 8 + ii;
            float2* op = reinterpret_cast<float2*>(out + ((size_t)b * Tq + t) * Mq + 2 * p);
            float2 cur = *op;                 // base from k_dterm
            cur.x = fmaf(r.x, inv, cur.x);
            cur.y = fmaf(r.y, inv, cur.y);
            *op = cur;
        }
    }
}

// ---------------- launch ------------------------------------------------------
extern "C" void kernel_launch(void* const* d_in, const int* in_sizes, int n_in,
                              void* d_out, int out_size) {
    const float* x     = (const float*)d_in[0];
    const float* R     = (const float*)d_in[1];
    const float* theta = (const float*)d_in[2];
    const float* lnC_r = (const float*)d_in[3];
    const float* lnC_i = (const float*)d_in[4];
    const float* Dmat  = (const float*)d_in[5];
    const float* Dov   = (const float*)d_in[6];
    float* out = (float*)d_out;

    k_pre<<<1, dim3(32, 32)>>>(theta);
    k_cp<<<(Kq * Nq * Mq + 255) / 256, 256>>>(lnC_r, lnC_i);
    k_xp<<<dim3(Tq / 32, Bq), 256>>>(x, R);
    k_part<<<(Bq * Kq * Cq) / 8, 256>>>();
    k_scan<<<Bq * Kq, 32>>>();
    k_dterm<<<(Bq * Tq) / 8, 128>>>(Dmat, Dov, out);
    k_main<<<dim3(Cq, Bq), 288>>>(out);
}

// round 6
// speedup vs baseline: 1.0725x; 1.0515x over previous
#include <cuda_runtime.h>

#define Bq 8
#define Tq 2048
#define Dq 128
#define Kq 32
#define Nq 32
#define HNq 16
#define Mq 128
#define Lq 32
#define Cq 64            // Tq / Lq
#define ROWS (Bq*Tq)     // 16384 GEMM rows
#define KDIM (Kq*Nq*2)   // 2048 GEMM inner dim

// ---------------- device scratch (static; no allocation at launch) ----------
__device__ float  g_xp[Bq][Kq][Tq];          // projected input [b][k][t]
__device__ float2 g_lam[Kq][Nq];
__device__ float2 g_lamL[Kq][Nq];
__device__ float2 g_Bp[Kq][Nq];
__device__ float  g_C[KDIM][Mq];             // row k*64+n: Re(Cp); row k*64+32+n: -Im(Cp)
__device__ float  g_A[(size_t)ROWS * KDIM];  // state matrix (134 MB)

#define FMA2(d, a, b) asm("fma.rn.f32x2 %0, %1, %2, %0;" : "+l"(d) : "l"(a), "l"(b))

// ---------------- K0: lambda/lamL/Bp (block 0) + C matrix (blocks 1..) ------
__global__ void k_precp(const float* __restrict__ theta,
                        const float* __restrict__ lnr,
                        const float* __restrict__ lni) {
    if (blockIdx.x == 0) {
        __shared__ float ph[Kq][Nq];
        int k = threadIdx.x >> 5;
        int j = threadIdx.x & 31;
        float th = (j < HNq) ? theta[k * HNq + j] : -theta[k * HNq + (j - HNq)];
        ph[k][j] = th;
        __syncthreads();

        double phj = (double)ph[k][j];
        g_lam[k][j]  = make_float2((float)cos(phj), (float)sin(phj));
        double aL = phj * (double)Lq;
        g_lamL[k][j] = make_float2((float)cos(aL), (float)sin(aL));

        double lr = 0.0, li = 0.0;
        for (int i = 0; i < Nq; i++) {
            if (i == j) continue;
            double d  = (double)ph[k][i] - phj;
            double wr = 1.0 - cos(d);
            double wi = -sin(d);
            lr += 0.5 * log(wr * wr + wi * wi);
            li += atan2(wi, wr);
        }
        double mag = exp(-lr);
        g_Bp[k][j] = make_float2((float)(mag * cos(-li)), (float)(mag * sin(-li)));
    } else {
        int idx = (blockIdx.x - 1) * 1024 + threadIdx.x;   // over K*N*M = 131072
        if (idx < Kq * Nq * Mq) {
            int k = idx >> 12;          // /(Nq*Mq)
            int n = (idx >> 7) & 31;
            int m = idx & 127;
            float r = expf(lnr[idx]);
            float a = lni[idx];
            g_C[k * 64 + n][m]      =  r * cosf(a);
            g_C[k * 64 + 32 + n][m] = -r * sinf(a);
        }
    }
}

// ---------------- K1: xp = x @ R, transposed to [b][k][t] --------------------
__global__ void k_xp(const float* __restrict__ x, const float* __restrict__ R) {
    __shared__ float xs[32][129];
    __shared__ float Rs[Dq][Kq];
    const int b  = blockIdx.y;
    const int t0 = blockIdx.x * 32;
    const int tid = threadIdx.x;

    for (int i = tid; i < Dq * Kq; i += 256) ((float*)Rs)[i] = R[i];
    for (int i = tid; i < 32 * Dq; i += 256) {
        int tl = i >> 7, d = i & 127;
        xs[tl][d] = x[((size_t)b * Tq + t0 + tl) * Dq + d];
    }
    __syncthreads();

    const int tl = tid & 31;
    const int k0 = tid >> 5;
    float acc[4] = {0.f, 0.f, 0.f, 0.f};
    for (int d = 0; d < Dq; d++) {
        float xv = xs[tl][d];
        #pragma unroll
        for (int j = 0; j < 4; j++) acc[j] = fmaf(xv, Rs[d][k0 + 8 * j], acc[j]);
    }
    #pragma unroll
    for (int j = 0; j < 4; j++) g_xp[b][k0 + 8 * j][t0 + tl] = acc[j];
}

// ---------------- K2: partials + cross-chunk scan + replay -> A --------------
// One block per (b,k): 8 warps. Warp w handles chunks w*8..w*8+7.
__global__ __launch_bounds__(256) void k_states() {
    __shared__ float2 sP[Cq][Nq];   // chunk partials
    __shared__ float2 sS[Cq][Nq];   // chunk-start states
    const int b = blockIdx.x >> 5;
    const int k = blockIdx.x & 31;
    const int lane = threadIdx.x & 31;
    const int w = threadIdx.x >> 5;

    const float2 lam = g_lam[k][lane];
    const float2 bp  = g_Bp[k][lane];

    // phase 1: per-chunk partials
    for (int q = 0; q < 8; q++) {
        int c = w * 8 + q;
        const float* xp = &g_xp[b][k][c * Lq];
        float pr = 0.f, pi = 0.f;
        #pragma unroll
        for (int j = 0; j < Lq; j++) {
            float xv = xp[j];
            float nr = fmaf(lam.x, pr, fmaf(-lam.y, pi, bp.x * xv));
            float ni = fmaf(lam.y, pr, fmaf(lam.x, pi, bp.y * xv));
            pr = nr; pi = ni;
        }
        sP[c][lane] = make_float2(pr, pi);
    }
    __syncthreads();

    // phase 2: cross-chunk scan (warp 0)
    if (w == 0) {
        float2 lL = g_lamL[k][lane];
        float sr = 0.f, si = 0.f;
        for (int c = 0; c < Cq; c++) {
            sS[c][lane] = make_float2(sr, si);
            float2 p = sP[c][lane];
            float nr = fmaf(lL.x, sr, fmaf(-lL.y, si, p.x));
            float ni = fmaf(lL.y, sr, fmaf(lL.x, si, p.y));
            sr = nr; si = ni;
        }
    }
    __syncthreads();

    // phase 3: replay each chunk, write state matrix A
    for (int q = 0; q < 8; q++) {
        int c = w * 8 + q;
        const float* xp = &g_xp[b][k][c * Lq];
        float2 s = sS[c][lane];
        size_t rb = ((size_t)b * Tq + c * Lq) * KDIM + k * 64;
        #pragma unroll
        for (int i = 0; i < Lq; i++) {
            g_A[rb + (size_t)i * KDIM + lane]      = s.x;   // sr -> col k*64+n
            g_A[rb + (size_t)i * KDIM + 32 + lane] = s.y;   // si -> col k*64+32+n
            float xv = xp[i];
            float nr = fmaf(lam.x, s.x, fmaf(-lam.y, s.y, bp.x * xv));
            float ni = fmaf(lam.y, s.x, fmaf(lam.x, s.y, bp.y * xv));
            s.x = nr; s.y = ni;
        }
    }
}

// ---------------- K3: SGEMM out = A[16384x2048] * C[2048x128] / 32 -----------
#define MT 64
#define KT 16
#define NTILES (KDIM / KT)   // 128

__global__ __launch_bounds__(256, 2) void k_gemm(float* __restrict__ out) {
    __shared__ float2 As[2][KT][66];   // [kk][t], value duplicated (a,a)
    __shared__ float4 Cs[2][KT][Mq / 4];
    const int tid = threadIdx.x;
    const int tg = tid >> 5;               // warp id -> t rows tg*8..+7
    const int mg = tid & 31;               // m group -> cols mg*4..+3
    const size_t row0 = (size_t)blockIdx.x * MT;
    const float* Ab = g_A + row0 * KDIM;

    const int ar = tid >> 2;               // 0..63 local A row
    const int ac = (tid & 3) * 4;          // k-col offset (float4)
    const int crr = tid >> 4;              // 0..15 C row
    const int ccc = (tid & 15) * 8;        // C m offset (2 float4)

    float4 av, cv0, cv1;
    av  = *(const float4*)(Ab + (size_t)ar * KDIM + ac);
    cv0 = *(const float4*)(&g_C[crr][ccc]);
    cv1 = *(const float4*)(&g_C[crr][ccc + 4]);
    As[0][ac + 0][ar] = make_float2(av.x, av.x);
    As[0][ac + 1][ar] = make_float2(av.y, av.y);
    As[0][ac + 2][ar] = make_float2(av.z, av.z);
    As[0][ac + 3][ar] = make_float2(av.w, av.w);
    Cs[0][crr][(ccc >> 2)]     = cv0;
    Cs[0][crr][(ccc >> 2) + 1] = cv1;
    __syncthreads();

    unsigned long long acc[8][2];
    #pragma unroll
    for (int i = 0; i < 8; i++) { acc[i][0] = 0ull; acc[i][1] = 0ull; }

    for (int kt = 0; kt < NTILES; kt++) {
        const int buf = kt & 1;
        if (kt + 1 < NTILES) {
            int k0 = (kt + 1) * KT;
            av  = *(const float4*)(Ab + (size_t)ar * KDIM + k0 + ac);
            cv0 = *(const float4*)(&g_C[k0 + crr][ccc]);
            cv1 = *(const float4*)(&g_C[k0 + crr][ccc + 4]);
        }
        #pragma unroll
        for (int kk = 0; kk < KT; kk++) {
            ulonglong2 a01 = *(const ulonglong2*)&As[buf][kk][tg * 8 + 0];
            ulonglong2 a23 = *(const ulonglong2*)&As[buf][kk][tg * 8 + 2];
            ulonglong2 a45 = *(const ulonglong2*)&As[buf][kk][tg * 8 + 4];
            ulonglong2 a67 = *(const ulonglong2*)&As[buf][kk][tg * 8 + 6];
            ulonglong2 cc2 = ((const ulonglong2*)&Cs[buf][kk][0])[mg];
            FMA2(acc[0][0], a01.x, cc2.x); FMA2(acc[0][1], a01.x, cc2.y);
            FMA2(acc[1][0], a01.y, cc2.x); FMA2(acc[1][1], a01.y, cc2.y);
            FMA2(acc[2][0], a23.x, cc2.x); FMA2(acc[2][1], a23.x, cc2.y);
            FMA2(acc[3][0], a23.y, cc2.x); FMA2(acc[3][1], a23.y, cc2.y);
            FMA2(acc[4][0], a45.x, cc2.x); FMA2(acc[4][1], a45.x, cc2.y);
            FMA2(acc[5][0], a45.y, cc2.x); FMA2(acc[5][1], a45.y, cc2.y);
            FMA2(acc[6][0], a67.x, cc2.x); FMA2(acc[6][1], a67.x, cc2.y);
            FMA2(acc[7][0], a67.y, cc2.x); FMA2(acc[7][1], a67.y, cc2.y);
        }
        if (kt + 1 < NTILES) {
            const int nb = buf ^ 1;
            As[nb][ac + 0][ar] = make_float2(av.x, av.x);
            As[nb][ac + 1][ar] = make_float2(av.y, av.y);
            As[nb][ac + 2][ar] = make_float2(av.z, av.z);
            As[nb][ac + 3][ar] = make_float2(av.w, av.w);
            Cs[nb][crr][(ccc >> 2)]     = cv0;
            Cs[nb][crr][(ccc >> 2) + 1] = cv1;
            __syncthreads();
        }
    }

    const float inv = 1.0f / 32.0f;
    #pragma unroll
    for (int i = 0; i < 8; i++) {
        float2 p0 = *reinterpret_cast<float2*>(&acc[i][0]);
        float2 p1 = *reinterpret_cast<float2*>(&acc[i][1]);
        float4 o = make_float4(p0.x * inv, p0.y * inv, p1.x * inv, p1.y * inv);
        *(float4*)(out + (row0 + tg * 8 + i) * Mq + mg * 4) = o;
    }
}

// ---------------- K4: out += xp @ D / 32 + Do --------------------------------
__global__ void k_dterm(const float* __restrict__ Dmat, const float* __restrict__ Dov,
                        float* __restrict__ out) {
    __shared__ float sxp[8][33];
    const int m   = threadIdx.x;
    const int bt0 = blockIdx.x * 8;
    for (int i = threadIdx.x; i < 8 * Kq; i += 128) {
        int r = i >> 5, k = i & 31;
        int bt = bt0 + r;
        sxp[r][k] = g_xp[bt >> 11][k][bt & 2047];
    }
    __syncthreads();
    float dov = Dov[m];
    for (int r = 0; r < 8; r++) {
        float acc = 0.f;
        #pragma unroll 8
        for (int k = 0; k < Kq; k++) acc = fmaf(sxp[r][k], Dmat[k * Mq + m], acc);
        size_t idx = (size_t)(bt0 + r) * Mq + m;
        out[idx] = out[idx] + fmaf(acc, 1.0f / 32.0f, dov);
    }
}

// ---------------- launch ------------------------------------------------------
extern "C" void kernel_launch(void* const* d_in, const int* in_sizes, int n_in,
                              void* d_out, int out_size) {
    const float* x     = (const float*)d_in[0];
    const float* R     = (const float*)d_in[1];
    const float* theta = (const float*)d_in[2];
    const float* lnC_r = (const float*)d_in[3];
    const float* lnC_i = (const float*)d_in[4];
    const float* Dmat  = (const float*)d_in[5];
    const float* Dov   = (const float*)d_in[6];
    float* out = (float*)d_out;

    k_precp<<<1 + (Kq * Nq * Mq + 1023) / 1024, 1024>>>(theta, lnC_r, lnC_i);  // 0
    k_xp<<<dim3(Tq / 32, Bq), 256>>>(x, R);                                    // 1
    k_states<<<Bq * Kq, 256>>>();                                              // 2
    k_gemm<<<ROWS / MT, 256>>>(out);                                           // 3 (profiled slot)
    k_dterm<<<(Bq * Tq) / 8, 128>>>(Dmat, Dov, out);                           // 4
}

// round 8
// speedup vs baseline: 4.2725x; 3.9835x over previous
#include <cuda_runtime.h>
#include <math.h>

#define Bq 8
#define Tq 2048
#define Dq 128
#define Kq 32
#define Nq 32
#define HNq 16
#define Mq 128
#define Lq 32
#define Cq 64            // Tq / Lq
#define ROWS (Bq*Tq)     // 16384 GEMM rows
#define KDIM (Kq*Nq*2)   // 2048 GEMM inner dim

// ---------------- device scratch (static; no allocation at launch) ----------
__device__ float  g_xp[Bq][Kq][Tq];          // projected input [b][k][t]
__device__ float2 g_lam[Kq][Nq];
__device__ float2 g_lamL[Kq][Nq];
__device__ float2 g_Bp[Kq][Nq];
__device__ float  g_C[KDIM][Mq];             // row k*64+n: Re(Cp); row k*64+32+n: -Im(Cp)
__device__ float  g_A[(size_t)ROWS * KDIM];  // state matrix (134 MB)

#define FMA2(d, a, b) asm("fma.rn.f32x2 %0, %1, %2, %0;" : "+l"(d) : "l"(a), "l"(b))

// ---------------- K0: lambda/lamL/Bp (blocks 0..31, fp32) + C (blocks 32..) --
// FP64 transcendentals removed: per-pair term uses 1 - e^{id} = 2 sin(d/2) e^{i(d/2 - sgn(d) pi/2)}.
// Double used ONLY for add/rint range reductions (no DFMA-heavy software trig).
__global__ void k_precp(const float* __restrict__ theta,
                        const float* __restrict__ lnr,
                        const float* __restrict__ lni) {
    const int bx = blockIdx.x;
    if (bx < Kq) {
        if (threadIdx.x >= Nq) return;
        const int k = bx;
        const int j = threadIdx.x;
        __shared__ float th[HNq];
        if (j < HNq) th[j] = theta[k * HNq + j];
        __syncwarp(0xFFFFFFFF);

        const float phj = (j < HNq) ? th[j] : -th[j - HNq];
        g_lam[k][j] = make_float2(cosf(phj), sinf(phj));

        // lambda^L: reduce 32*theta mod 2pi in double (exact enough), trig in float
        double aL  = (double)phj * 32.0;
        double red = aL - rint(aL * (0.5 / M_PI)) * (2.0 * M_PI);
        float  rf  = (float)red;
        g_lamL[k][j] = make_float2(cosf(rf), sinf(rf));

        // lnBp = -sum_{i != j} log(1 - e^{i(th_i - th_j)})
        float  lr  = 0.0f;   // sum of log magnitudes
        double liD = 0.0;    // sum of phases (double adds only)
        #pragma unroll
        for (int i = 0; i < Nq; i++) {
            if (i == j) continue;
            float phi = (i < HNq) ? th[i] : -th[i - HNq];
            float d   = phi - phj;
            float s   = sinf(0.5f * d);
            lr  += logf(2.0f * fabsf(s));
            liD += (double)(0.5f * d) - copysign(0.5 * M_PI, (double)d);
        }
        double phiB = -liD;
        phiB -= rint(phiB * (0.5 / M_PI)) * (2.0 * M_PI);
        float mag = expf(-lr);
        float pb  = (float)phiB;
        g_Bp[k][j] = make_float2(mag * cosf(pb), mag * sinf(pb));
    } else {
        int idx = (bx - Kq) * 256 + threadIdx.x;   // over K*N*M = 131072
        if (idx < Kq * Nq * Mq) {
            int k = idx >> 12;
            int n = (idx >> 7) & 31;
            int m = idx & 127;
            float r = expf(lnr[idx]);
            float a = lni[idx];
            g_C[k * 64 + n][m]      =  r * cosf(a);
            g_C[k * 64 + 32 + n][m] = -r * sinf(a);
        }
    }
}

// ---------------- K1: xp = x @ R, transposed to [b][k][t] --------------------
__global__ void k_xp(const float* __restrict__ x, const float* __restrict__ R) {
    __shared__ float xs[32][129];
    __shared__ float Rs[Dq][Kq];
    const int b  = blockIdx.y;
    const int t0 = blockIdx.x * 32;
    const int tid = threadIdx.x;

    for (int i = tid; i < Dq * Kq; i += 256) ((float*)Rs)[i] = R[i];
    for (int i = tid; i < 32 * Dq; i += 256) {
        int tl = i >> 7, d = i & 127;
        xs[tl][d] = x[((size_t)b * Tq + t0 + tl) * Dq + d];
    }
    __syncthreads();

    const int tl = tid & 31;
    const int k0 = tid >> 5;
    float acc[4] = {0.f, 0.f, 0.f, 0.f};
    for (int d = 0; d < Dq; d++) {
        float xv = xs[tl][d];
        #pragma unroll
        for (int j = 0; j < 4; j++) acc[j] = fmaf(xv, Rs[d][k0 + 8 * j], acc[j]);
    }
    #pragma unroll
    for (int j = 0; j < 4; j++) g_xp[b][k0 + 8 * j][t0 + tl] = acc[j];
}

// ---------------- K2: partials + cross-chunk scan + replay -> A --------------
__global__ __launch_bounds__(256) void k_states() {
    __shared__ float2 sP[Cq][Nq];
    __shared__ float2 sS[Cq][Nq];
    const int b = blockIdx.x >> 5;
    const int k = blockIdx.x & 31;
    const int lane = threadIdx.x & 31;
    const int w = threadIdx.x >> 5;

    const float2 lam = g_lam[k][lane];
    const float2 bp  = g_Bp[k][lane];

    for (int q = 0; q < 8; q++) {
        int c = w * 8 + q;
        const float* xp = &g_xp[b][k][c * Lq];
        float pr = 0.f, pi = 0.f;
        #pragma unroll
        for (int j = 0; j < Lq; j++) {
            float xv = xp[j];
            float nr = fmaf(lam.x, pr, fmaf(-lam.y, pi, bp.x * xv));
            float ni = fmaf(lam.y, pr, fmaf(lam.x, pi, bp.y * xv));
            pr = nr; pi = ni;
        }
        sP[c][lane] = make_float2(pr, pi);
    }
    __syncthreads();

    if (w == 0) {
        float2 lL = g_lamL[k][lane];
        float sr = 0.f, si = 0.f;
        for (int c = 0; c < Cq; c++) {
            sS[c][lane] = make_float2(sr, si);
            float2 p = sP[c][lane];
            float nr = fmaf(lL.x, sr, fmaf(-lL.y, si, p.x));
            float ni = fmaf(lL.y, sr, fmaf(lL.x, si, p.y));
            sr = nr; si = ni;
        }
    }
    __syncthreads();

    for (int q = 0; q < 8; q++) {
        int c = w * 8 + q;
        const float* xp = &g_xp[b][k][c * Lq];
        float2 s = sS[c][lane];
        size_t rb = ((size_t)b * Tq + c * Lq) * KDIM + k * 64;
        #pragma unroll
        for (int i = 0; i < Lq; i++) {
            g_A[rb + (size_t)i * KDIM + lane]      = s.x;
            g_A[rb + (size_t)i * KDIM + 32 + lane] = s.y;
            float xv = xp[i];
            float nr = fmaf(lam.x, s.x, fmaf(-lam.y, s.y, bp.x * xv));
            float ni = fmaf(lam.y, s.x, fmaf(lam.x, s.y, bp.y * xv));
            s.x = nr; s.y = ni;
        }
    }
}

// ---------------- K3: SGEMM out = A[16384x2048] * C[2048x128] / 32 -----------
#define MT 64
#define KT 16
#define NTILES (KDIM / KT)   // 128

__global__ __launch_bounds__(256, 2) void k_gemm(float* __restrict__ out) {
    __shared__ float2 As[2][KT][66];
    __shared__ float4 Cs[2][KT][Mq / 4];
    const int tid = threadIdx.x;
    const int tg = tid >> 5;
    const int mg = tid & 31;
    const size_t row0 = (size_t)blockIdx.x * MT;
    const float* Ab = g_A + row0 * KDIM;

    const int ar = tid >> 2;
    const int ac = (tid & 3) * 4;
    const int crr = tid >> 4;
    const int ccc = (tid & 15) * 8;

    float4 av, cv0, cv1;
    av  = *(const float4*)(Ab + (size_t)ar * KDIM + ac);
    cv0 = *(const float4*)(&g_C[crr][ccc]);
    cv1 = *(const float4*)(&g_C[crr][ccc + 4]);
    As[0][ac + 0][ar] = make_float2(av.x, av.x);
    As[0][ac + 1][ar] = make_float2(av.y, av.y);
    As[0][ac + 2][ar] = make_float2(av.z, av.z);
    As[0][ac + 3][ar] = make_float2(av.w, av.w);
    Cs[0][crr][(ccc >> 2)]     = cv0;
    Cs[0][crr][(ccc >> 2) + 1] = cv1;
    __syncthreads();

    unsigned long long acc[8][2];
    #pragma unroll
    for (int i = 0; i < 8; i++) { acc[i][0] = 0ull; acc[i][1] = 0ull; }

    for (int kt = 0; kt < NTILES; kt++) {
        const int buf = kt & 1;
        if (kt + 1 < NTILES) {
            int k0 = (kt + 1) * KT;
            av  = *(const float4*)(Ab + (size_t)ar * KDIM + k0 + ac);
            cv0 = *(const float4*)(&g_C[k0 + crr][ccc]);
            cv1 = *(const float4*)(&g_C[k0 + crr][ccc + 4]);
        }
        #pragma unroll
        for (int kk = 0; kk < KT; kk++) {
            ulonglong2 a01 = *(const ulonglong2*)&As[buf][kk][tg * 8 + 0];
            ulonglong2 a23 = *(const ulonglong2*)&As[buf][kk][tg * 8 + 2];
            ulonglong2 a45 = *(const ulonglong2*)&As[buf][kk][tg * 8 + 4];
            ulonglong2 a67 = *(const ulonglong2*)&As[buf][kk][tg * 8 + 6];
            ulonglong2 cc2 = ((const ulonglong2*)&Cs[buf][kk][0])[mg];
            FMA2(acc[0][0], a01.x, cc2.x); FMA2(acc[0][1], a01.x, cc2.y);
            FMA2(acc[1][0], a01.y, cc2.x); FMA2(acc[1][1], a01.y, cc2.y);
            FMA2(acc[2][0], a23.x, cc2.x); FMA2(acc[2][1], a23.x, cc2.y);
            FMA2(acc[3][0], a23.y, cc2.x); FMA2(acc[3][1], a23.y, cc2.y);
            FMA2(acc[4][0], a45.x, cc2.x); FMA2(acc[4][1], a45.x, cc2.y);
            FMA2(acc[5][0], a45.y, cc2.x); FMA2(acc[5][1], a45.y, cc2.y);
            FMA2(acc[6][0], a67.x, cc2.x); FMA2(acc[6][1], a67.x, cc2.y);
            FMA2(acc[7][0], a67.y, cc2.x); FMA2(acc[7][1], a67.y, cc2.y);
        }
        if (kt + 1 < NTILES) {
            const int nb = buf ^ 1;
            As[nb][ac + 0][ar] = make_float2(av.x, av.x);
            As[nb][ac + 1][ar] = make_float2(av.y, av.y);
            As[nb][ac + 2][ar] = make_float2(av.z, av.z);
            As[nb][ac + 3][ar] = make_float2(av.w, av.w);
            Cs[nb][crr][(ccc >> 2)]     = cv0;
            Cs[nb][crr][(ccc >> 2) + 1] = cv1;
            __syncthreads();
        }
    }

    const float inv = 1.0f / 32.0f;
    #pragma unroll
    for (int i = 0; i < 8; i++) {
        float2 p0 = *reinterpret_cast<float2*>(&acc[i][0]);
        float2 p1 = *reinterpret_cast<float2*>(&acc[i][1]);
        float4 o = make_float4(p0.x * inv, p0.y * inv, p1.x * inv, p1.y * inv);
        *(float4*)(out + (row0 + tg * 8 + i) * Mq + mg * 4) = o;
    }
}

// ---------------- K4: out += xp @ D / 32 + Do --------------------------------
__global__ void k_dterm(const float* __restrict__ Dmat, const float* __restrict__ Dov,
                        float* __restrict__ out) {
    __shared__ float sxp[8][33];
    const int m   = threadIdx.x;
    const int bt0 = blockIdx.x * 8;
    for (int i = threadIdx.x; i < 8 * Kq; i += 128) {
        int r = i >> 5, k = i & 31;
        int bt = bt0 + r;
        sxp[r][k] = g_xp[bt >> 11][k][bt & 2047];
    }
    __syncthreads();
    float dov = Dov[m];
    for (int r = 0; r < 8; r++) {
        float acc = 0.f;
        #pragma unroll 8
        for (int k = 0; k < Kq; k++) acc = fmaf(sxp[r][k], Dmat[k * Mq + m], acc);
        size_t idx = (size_t)(bt0 + r) * Mq + m;
        out[idx] = out[idx] + fmaf(acc, 1.0f / 32.0f, dov);
    }
}

// ---------------- launch ------------------------------------------------------
extern "C" void kernel_launch(void* const* d_in, const int* in_sizes, int n_in,
                              void* d_out, int out_size) {
    const float* x     = (const float*)d_in[0];
    const float* R     = (const float*)d_in[1];
    const float* theta = (const float*)d_in[2];
    const float* lnC_r = (const float*)d_in[3];
    const float* lnC_i = (const float*)d_in[4];
    const float* Dmat  = (const float*)d_in[5];
    const float* Dov   = (const float*)d_in[6];
    float* out = (float*)d_out;

    k_precp<<<Kq + (Kq * Nq * Mq + 255) / 256, 256>>>(theta, lnC_r, lnC_i);    // 0
    k_xp<<<dim3(Tq / 32, Bq), 256>>>(x, R);                                    // 1
    k_states<<<Bq * Kq, 256>>>();                                              // 2
    k_gemm<<<ROWS / MT, 256>>>(out);                                           // 3
    k_dterm<<<(Bq * Tq) / 8, 128>>>(Dmat, Dov, out);                           // 4
}

// round 9
// speedup vs baseline: 6.5432x; 1.5315x over previous
#include <cuda_runtime.h>
#include <math.h>

#define Bq 8
#define Tq 2048
#define Dq 128
#define Kq 32
#define Nq 32
#define HNq 16
#define Mq 128
#define Lq 32
#define Cq 64            // Tq / Lq
#define ROWS (Bq*Tq)     // 16384 GEMM rows
#define KD2 1024         // GEMM inner dim after conjugate folding (32k * 32)

// ---------------- device scratch (static; no allocation at launch) ----------
__device__ float  g_xp[Bq][Kq][Tq];          // projected input [b][k][t]
__device__ float2 g_lam[Kq][Nq];
__device__ float2 g_lamL[Kq][Nq];
__device__ float2 g_Bp[Kq][Nq];
__device__ float  g_C[KD2][Mq];              // row k*32+j (j<16): Cr_j+Cr_{j+16}; row k*32+16+j: Ci_{j+16}-Ci_j
__device__ float  g_A[(size_t)ROWS * KD2];   // folded state matrix (67 MB)

#define FMA2(d, a, b) asm("fma.rn.f32x2 %0, %1, %2, %0;" : "+l"(d) : "l"(a), "l"(b))

// ---------------- K0: lambda/lamL/Bp (blocks 0..31) + folded C (blocks 32..) -
__global__ void k_precp(const float* __restrict__ theta,
                        const float* __restrict__ lnr,
                        const float* __restrict__ lni) {
    const int bx = blockIdx.x;
    if (bx < Kq) {
        if (threadIdx.x >= Nq) return;
        const int k = bx;
        const int j = threadIdx.x;
        __shared__ float th[HNq];
        if (j < HNq) th[j] = theta[k * HNq + j];
        __syncwarp(0xFFFFFFFF);

        const float phj = (j < HNq) ? th[j] : -th[j - HNq];
        g_lam[k][j] = make_float2(cosf(phj), sinf(phj));

        double aL  = (double)phj * 32.0;
        double red = aL - rint(aL * (0.5 / M_PI)) * (2.0 * M_PI);
        float  rf  = (float)red;
        g_lamL[k][j] = make_float2(cosf(rf), sinf(rf));

        // lnBp = -sum_{i != j} log(1 - e^{i(th_i - th_j)});
        // 1 - e^{id} = 2 sin(d/2) e^{i(d/2 - sgn(d) pi/2)}   (fp32 trig only)
        float  lr  = 0.0f;
        double liD = 0.0;
        #pragma unroll
        for (int i = 0; i < Nq; i++) {
            if (i == j) continue;
            float phi = (i < HNq) ? th[i] : -th[i - HNq];
            float d   = phi - phj;
            float s   = sinf(0.5f * d);
            lr  += logf(2.0f * fabsf(s));
            liD += (double)(0.5f * d) - copysign(0.5 * M_PI, (double)d);
        }
        double phiB = -liD;
        phiB -= rint(phiB * (0.5 / M_PI)) * (2.0 * M_PI);
        float mag = expf(-lr);
        float pb  = (float)phiB;
        g_Bp[k][j] = make_float2(mag * cosf(pb), mag * sinf(pb));
    } else {
        // folded C: one thread per (k, j<16, m); reads n=j and n=j+16
        int idx = (bx - Kq) * 256 + threadIdx.x;   // 0 .. 65535
        if (idx < Kq * HNq * Mq) {
            int k = idx >> 11;          // /(16*128)
            int j = (idx >> 7) & 15;
            int m = idx & 127;
            int i1 = (k * Nq + j) * Mq + m;
            int i2 = (k * Nq + j + HNq) * Mq + m;
            float r1 = expf(lnr[i1]), a1 = lni[i1];
            float r2 = expf(lnr[i2]), a2 = lni[i2];
            g_C[k * 32 + j][m]      = fmaf(r1, cosf(a1), r2 * cosf(a2));   // Cr_j + Cr_{j+16}
            g_C[k * 32 + 16 + j][m] = fmaf(r2, sinf(a2), -r1 * sinf(a1));  // Ci_{j+16} - Ci_j
        }
    }
}

// ---------------- K1: xp = x @ R, transposed to [b][k][t] --------------------
__global__ void k_xp(const float* __restrict__ x, const float* __restrict__ R) {
    __shared__ float xs[32][129];
    __shared__ float Rs[Dq][Kq];
    const int b  = blockIdx.y;
    const int t0 = blockIdx.x * 32;
    const int tid = threadIdx.x;

    for (int i = tid; i < Dq * Kq; i += 256) ((float*)Rs)[i] = R[i];
    for (int i = tid; i < 32 * Dq; i += 256) {
        int tl = i >> 7, d = i & 127;
        xs[tl][d] = x[((size_t)b * Tq + t0 + tl) * Dq + d];
    }
    __syncthreads();

    const int tl = tid & 31;
    const int k0 = tid >> 5;
    float acc[4] = {0.f, 0.f, 0.f, 0.f};
    for (int d = 0; d < Dq; d++) {
        float xv = xs[tl][d];
        #pragma unroll
        for (int j = 0; j < 4; j++) acc[j] = fmaf(xv, Rs[d][k0 + 8 * j], acc[j]);
    }
    #pragma unroll
    for (int j = 0; j < 4; j++) g_xp[b][k0 + 8 * j][t0 + tl] = acc[j];
}

// ---------------- K2: partials + cross-chunk scan + replay -> folded A -------
// lanes 16..31 compute the conjugate branch; their s.y = -si of partner lane.
__global__ __launch_bounds__(256) void k_states() {
    __shared__ float2 sP[Cq][Nq];
    __shared__ float2 sS[Cq][Nq];
    const int b = blockIdx.x >> 5;
    const int k = blockIdx.x & 31;
    const int lane = threadIdx.x & 31;
    const int w = threadIdx.x >> 5;

    const float2 lam = g_lam[k][lane];
    const float2 bp  = g_Bp[k][lane];

    for (int q = 0; q < 8; q++) {
        int c = w * 8 + q;
        const float* xp = &g_xp[b][k][c * Lq];
        float pr = 0.f, pi = 0.f;
        #pragma unroll
        for (int j = 0; j < Lq; j++) {
            float xv = xp[j];
            float nr = fmaf(lam.x, pr, fmaf(-lam.y, pi, bp.x * xv));
            float ni = fmaf(lam.y, pr, fmaf(lam.x, pi, bp.y * xv));
            pr = nr; pi = ni;
        }
        sP[c][lane] = make_float2(pr, pi);
    }
    __syncthreads();

    if (w == 0) {
        float2 lL = g_lamL[k][lane];
        float sr = 0.f, si = 0.f;
        for (int c = 0; c < Cq; c++) {
            sS[c][lane] = make_float2(sr, si);
            float2 p = sP[c][lane];
            float nr = fmaf(lL.x, sr, fmaf(-lL.y, si, p.x));
            float ni = fmaf(lL.y, sr, fmaf(lL.x, si, p.y));
            sr = nr; si = ni;
        }
    }
    __syncthreads();

    for (int q = 0; q < 8; q++) {
        int c = w * 8 + q;
        const float* xp = &g_xp[b][k][c * Lq];
        float2 s = sS[c][lane];
        size_t rb = ((size_t)b * Tq + c * Lq) * KD2 + k * 32;
        #pragma unroll
        for (int i = 0; i < Lq; i++) {
            // lane<16: sr_lane ; lane>=16: -s.y = si of (lane-16). One coalesced float per lane.
            g_A[rb + (size_t)i * KD2 + lane] = (lane < HNq) ? s.x : -s.y;
            float xv = xp[i];
            float nr = fmaf(lam.x, s.x, fmaf(-lam.y, s.y, bp.x * xv));
            float ni = fmaf(lam.y, s.x, fmaf(lam.x, s.y, bp.y * xv));
            s.x = nr; s.y = ni;
        }
    }
}

// ---------------- K3: SGEMM out = A[16384x1024] * C[1024x128] / 32 -----------
// 128 threads, block tile 64t x 128m, per-thread 8t x 8m (m-packed FFMA2).
#define MT 64
#define KT 16
#define NT2 (KD2 / KT)   // 64

__global__ __launch_bounds__(128, 2) void k_gemm(float* __restrict__ out) {
    __shared__ float2 As[2][KT][66];    // dup (a,a), indexed [kk][t]
    __shared__ float  Cs[2][KT][132];   // natural, indexed [kk][m]
    const int tid = threadIdx.x;
    const int tg = tid >> 4;            // 0..7  -> t rows tg*8..+7
    const int mg = tid & 15;            // 0..15 -> m cols mg*8..+7
    const size_t row0 = (size_t)blockIdx.x * MT;
    const float* Ab = g_A + row0 * KD2;

    const int ar = tid >> 1;            // 0..63 : A row
    const int ac = (tid & 1) * 8;       // 0/8   : kk offset
    const int cr = tid >> 3;            // 0..15 : C row (kk)
    const int cc = (tid & 7) * 16;      // C m offset

    float4 av0, av1, cv0, cv1, cv2, cv3;
    av0 = *(const float4*)(Ab + (size_t)ar * KD2 + ac);
    av1 = *(const float4*)(Ab + (size_t)ar * KD2 + ac + 4);
    cv0 = *(const float4*)(&g_C[cr][cc]);
    cv1 = *(const float4*)(&g_C[cr][cc + 4]);
    cv2 = *(const float4*)(&g_C[cr][cc + 8]);
    cv3 = *(const float4*)(&g_C[cr][cc + 12]);
    As[0][ac + 0][ar] = make_float2(av0.x, av0.x);
    As[0][ac + 1][ar] = make_float2(av0.y, av0.y);
    As[0][ac + 2][ar] = make_float2(av0.z, av0.z);
    As[0][ac + 3][ar] = make_float2(av0.w, av0.w);
    As[0][ac + 4][ar] = make_float2(av1.x, av1.x);
    As[0][ac + 5][ar] = make_float2(av1.y, av1.y);
    As[0][ac + 6][ar] = make_float2(av1.z, av1.z);
    As[0][ac + 7][ar] = make_float2(av1.w, av1.w);
    *(float4*)(&Cs[0][cr][cc])      = cv0;
    *(float4*)(&Cs[0][cr][cc + 4])  = cv1;
    *(float4*)(&Cs[0][cr][cc + 8])  = cv2;
    *(float4*)(&Cs[0][cr][cc + 12]) = cv3;
    __syncthreads();

    unsigned long long acc[8][4];
    #pragma unroll
    for (int i = 0; i < 8; i++)
        #pragma unroll
        for (int p = 0; p < 4; p++) acc[i][p] = 0ull;

    for (int kt = 0; kt < NT2; kt++) {
        const int buf = kt & 1;
        if (kt + 1 < NT2) {
            int k0 = (kt + 1) * KT;
            av0 = *(const float4*)(Ab + (size_t)ar * KD2 + k0 + ac);
            av1 = *(const float4*)(Ab + (size_t)ar * KD2 + k0 + ac + 4);
            cv0 = *(const float4*)(&g_C[k0 + cr][cc]);
            cv1 = *(const float4*)(&g_C[k0 + cr][cc + 4]);
            cv2 = *(const float4*)(&g_C[k0 + cr][cc + 8]);
            cv3 = *(const float4*)(&g_C[k0 + cr][cc + 12]);
        }
        #pragma unroll
        for (int kk = 0; kk < KT; kk++) {
            ulonglong2 a01 = *(const ulonglong2*)&As[buf][kk][tg * 8 + 0];
            ulonglong2 a23 = *(const ulonglong2*)&As[buf][kk][tg * 8 + 2];
            ulonglong2 a45 = *(const ulonglong2*)&As[buf][kk][tg * 8 + 4];
            ulonglong2 a67 = *(const ulonglong2*)&As[buf][kk][tg * 8 + 6];
            ulonglong2 c01 = *(const ulonglong2*)&Cs[buf][kk][mg * 8];
            ulonglong2 c23 = *(const ulonglong2*)&Cs[buf][kk][mg * 8 + 4];
            FMA2(acc[0][0], a01.x, c01.x); FMA2(acc[0][1], a01.x, c01.y);
            FMA2(acc[0][2], a01.x, c23.x); FMA2(acc[0][3], a01.x, c23.y);
            FMA2(acc[1][0], a01.y, c01.x); FMA2(acc[1][1], a01.y, c01.y);
            FMA2(acc[1][2], a01.y, c23.x); FMA2(acc[1][3], a01.y, c23.y);
            FMA2(acc[2][0], a23.x, c01.x); FMA2(acc[2][1], a23.x, c01.y);
            FMA2(acc[2][2], a23.x, c23.x); FMA2(acc[2][3], a23.x, c23.y);
            FMA2(acc[3][0], a23.y, c01.x); FMA2(acc[3][1], a23.y, c01.y);
            FMA2(acc[3][2], a23.y, c23.x); FMA2(acc[3][3], a23.y, c23.y);
            FMA2(acc[4][0], a45.x, c01.x); FMA2(acc[4][1], a45.x, c01.y);
            FMA2(acc[4][2], a45.x, c23.x); FMA2(acc[4][3], a45.x, c23.y);
            FMA2(acc[5][0], a45.y, c01.x); FMA2(acc[5][1], a45.y, c01.y);
            FMA2(acc[5][2], a45.y, c23.x); FMA2(acc[5][3], a45.y, c23.y);
            FMA2(acc[6][0], a67.x, c01.x); FMA2(acc[6][1], a67.x, c01.y);
            FMA2(acc[6][2], a67.x, c23.x); FMA2(acc[6][3], a67.x, c23.y);
            FMA2(acc[7][0], a67.y, c01.x); FMA2(acc[7][1], a67.y, c01.y);
            FMA2(acc[7][2], a67.y, c23.x); FMA2(acc[7][3], a67.y, c23.y);
        }
        if (kt + 1 < NT2) {
            const int nb = buf ^ 1;
            As[nb][ac + 0][ar] = make_float2(av0.x, av0.x);
            As[nb][ac + 1][ar] = make_float2(av0.y, av0.y);
            As[nb][ac + 2][ar] = make_float2(av0.z, av0.z);
            As[nb][ac + 3][ar] = make_float2(av0.w, av0.w);
            As[nb][ac + 4][ar] = make_float2(av1.x, av1.x);
            As[nb][ac + 5][ar] = make_float2(av1.y, av1.y);
            As[nb][ac + 6][ar] = make_float2(av1.z, av1.z);
            As[nb][ac + 7][ar] = make_float2(av1.w, av1.w);
            *(float4*)(&Cs[nb][cr][cc])      = cv0;
            *(float4*)(&Cs[nb][cr][cc + 4])  = cv1;
            *(float4*)(&Cs[nb][cr][cc + 8])  = cv2;
            *(float4*)(&Cs[nb][cr][cc + 12]) = cv3;
            __syncthreads();
        }
    }

    const float inv = 1.0f / 32.0f;
    #pragma unroll
    for (int i = 0; i < 8; i++) {
        float2 p0 = *reinterpret_cast<float2*>(&acc[i][0]);
        float2 p1 = *reinterpret_cast<float2*>(&acc[i][1]);
        float2 p2 = *reinterpret_cast<float2*>(&acc[i][2]);
        float2 p3 = *reinterpret_cast<float2*>(&acc[i][3]);
        float* op = out + (row0 + tg * 8 + i) * Mq + mg * 8;
        *(float4*)(op)     = make_float4(p0.x * inv, p0.y * inv, p1.x * inv, p1.y * inv);
        *(float4*)(op + 4) = make_float4(p2.x * inv, p2.y * inv, p3.x * inv, p3.y * inv);
    }
}

// ---------------- K4: out += xp @ D / 32 + Do --------------------------------
__global__ void k_dterm(const float* __restrict__ Dmat, const float* __restrict__ Dov,
                        float* __restrict__ out) {
    __shared__ float sxp[8][33];
    const int m   = threadIdx.x;
    const int bt0 = blockIdx.x * 8;
    for (int i = threadIdx.x; i < 8 * Kq; i += 128) {
        int r = i >> 5, k = i & 31;
        int bt = bt0 + r;
        sxp[r][k] = g_xp[bt >> 11][k][bt & 2047];
    }
    __syncthreads();
    float dov = Dov[m];
    for (int r = 0; r < 8; r++) {
        float acc = 0.f;
        #pragma unroll 8
        for (int k = 0; k < Kq; k++) acc = fmaf(sxp[r][k], Dmat[k * Mq + m], acc);
        size_t idx = (size_t)(bt0 + r) * Mq + m;
        out[idx] = out[idx] + fmaf(acc, 1.0f / 32.0f, dov);
    }
}

// ---------------- launch ------------------------------------------------------
extern "C" void kernel_launch(void* const* d_in, const int* in_sizes, int n_in,
                              void* d_out, int out_size) {
    const float* x     = (const float*)d_in[0];
    const float* R     = (const float*)d_in[1];
    const float* theta = (const float*)d_in[2];
    const float* lnC_r = (const float*)d_in[3];
    const float* lnC_i = (const float*)d_in[4];
    const float* Dmat  = (const float*)d_in[5];
    const float* Dov   = (const float*)d_in[6];
    float* out = (float*)d_out;

    k_precp<<<Kq + (Kq * HNq * Mq + 255) / 256, 256>>>(theta, lnC_r, lnC_i);   // 0
    k_xp<<<dim3(Tq / 32, Bq), 256>>>(x, R);                                    // 1
    k_states<<<Bq * Kq, 256>>>();                                              // 2
    k_gemm<<<ROWS / MT, 128>>>(out);                                           // 3
    k_dterm<<<(Bq * Tq) / 8, 128>>>(Dmat, Dov, out);                           // 4
}